// round 12
// baseline (speedup 1.0000x reference)
#include <cuda_runtime.h>
#include <cstdint>

#define NB 16
#define NCH 128
#define NW 16384
#define NTILES 4096
#define GRID_SM 152
#define SCALE_F 0.17677669529663687f
#define LN_EPS 1e-5f

__device__ float g_S[NB * 4096];
__device__ float g_Z[NB * 128];
__device__ float g_M[NB * 128 * 128];

__device__ __forceinline__ uint32_t smem_u32(const void* p) {
    uint32_t a;
    asm("{ .reg .u64 t; cvta.to.shared.u64 t, %1; cvt.u32.u64 %0, t; }" : "=r"(a) : "l"(p));
    return a;
}
__device__ __forceinline__ void bf16_split2(float a, float b, uint32_t& h, uint32_t& l) {
    asm("cvt.rn.bf16x2.f32 %0, %1, %2;" : "=r"(h) : "f"(b), "f"(a));
    float ra = a - __uint_as_float(h << 16);
    float rb = b - __uint_as_float(h & 0xFFFF0000u);
    asm("cvt.rn.bf16x2.f32 %0, %1, %2;" : "=r"(l) : "f"(rb), "f"(ra));
}
__device__ __forceinline__ void ldsm_x4(uint32_t* a, uint32_t addr) {
    asm volatile("ldmatrix.sync.aligned.m8n8.x4.shared.b16 {%0,%1,%2,%3}, [%4];"
                 : "=r"(a[0]), "=r"(a[1]), "=r"(a[2]), "=r"(a[3]) : "r"(addr));
}
__device__ __forceinline__ void ldsm_x4t(uint32_t* a, uint32_t addr) {
    asm volatile("ldmatrix.sync.aligned.m8n8.x4.trans.shared.b16 {%0,%1,%2,%3}, [%4];"
                 : "=r"(a[0]), "=r"(a[1]), "=r"(a[2]), "=r"(a[3]) : "r"(addr));
}
__device__ __forceinline__ void mma16816(float* c, const uint32_t* a, const uint32_t* b) {
    asm volatile("mma.sync.aligned.m16n8k16.row.col.f32.bf16.bf16.f32 "
                 "{%0,%1,%2,%3},{%4,%5,%6,%7},{%8,%9},{%0,%1,%2,%3};"
                 : "+f"(c[0]), "+f"(c[1]), "+f"(c[2]), "+f"(c[3])
                 : "r"(a[0]), "r"(a[1]), "r"(a[2]), "r"(a[3]), "r"(b[0]), "r"(b[1]));
}

// fp32 rows of 128 -> two bf16 planes in smem, rows of 256B, XOR-16B swizzle
__device__ __forceinline__ void w_row_sts(char* sm, uint32_t oh, uint32_t ol,
                                          const float* __restrict__ src,
                                          int nrows, int tid, int nthreads) {
    for (int idx = tid * 4; idx < nrows * 128; idx += nthreads * 4) {
        int m = idx >> 7, k = idx & 127;
        float4 w = *(const float4*)(src + m * 128 + k);
        uint32_t h0, l0, h1, l1;
        bf16_split2(w.x, w.y, h0, l0);
        bf16_split2(w.z, w.w, h1, l1);
        uint32_t byte = (uint32_t)(m * 256) + (((uint32_t)(k * 2)) ^ (((uint32_t)m & 7) << 4));
        *(uint2*)(sm + oh + byte) = make_uint2(h0, h1);
        *(uint2*)(sm + ol + byte) = make_uint2(l0, l1);
    }
}

// ---------------------------------------------------------------------------
__global__ void k_zero() {
    int i = blockIdx.x * blockDim.x + threadIdx.x;
    if (i < NB * 4096) g_S[i] = 0.0f;
    else g_Z[i - NB * 4096] = 0.0f;
}

// ---------------------------------------------------------------------------
// k_kvctx: UNCHANGED from R10 (passing, 331.3us total)
#define O_XHI 131072u
#define O_XLO 147456u
#define O_EKH 163840u
#define O_EKL 180224u
#define O_VH  196608u
#define O_VL  212992u

__global__ void __launch_bounds__(256, 1)
k_kvctx(const float* __restrict__ x, const float* __restrict__ Wqkv) {
    extern __shared__ char sm[];
    const uint32_t smb = smem_u32(sm);
    const int tid = threadIdx.x, wid = tid >> 5, lane = tid & 31;
    const int mbase = wid * 32;
    const int h = wid >> 1, mh = wid & 1;

    w_row_sts(sm, 0u, 65536u, Wqkv + 128 * 128, 256, tid, 256);

    int per = (NTILES + GRID_SM - 1) / GRID_SM;   // 27
    int lo = blockIdx.x * per, hi = min(NTILES, lo + per);

    float CS[4][4];
    float zacc[4];
    int curb = -1;

    float4 px[8];
    if (lo < hi) {
        const float* xb = x + (size_t)(lo >> 8) * NCH * NW + (size_t)(lo & 255) * 64;
        #pragma unroll
        for (int it = 0; it < 8; it++) {
            int idx = tid * 4 + it * 1024;
            px[it] = *(const float4*)(xb + (size_t)(idx >> 6) * NW + (idx & 63));
        }
    }

    for (int tile = lo; tile < hi; tile++) {
        int b = tile >> 8;
        if (b != curb) {
            if (curb >= 0) {
                float* gS = g_S + curb * 4096 + h * 1024;
                int d0 = mh * 16 + (lane >> 2);
                #pragma unroll
                for (int nt = 0; nt < 4; nt++) {
                    int e = nt * 8 + 2 * (lane & 3);
                    atomicAdd(gS + d0 * 32 + e,           CS[nt][0]);
                    atomicAdd(gS + d0 * 32 + e + 1,       CS[nt][1]);
                    atomicAdd(gS + (d0 + 8) * 32 + e,     CS[nt][2]);
                    atomicAdd(gS + (d0 + 8) * 32 + e + 1, CS[nt][3]);
                }
                if (wid < 4 && (lane & 3) == 0) {
                    #pragma unroll
                    for (int mt = 0; mt < 2; mt++) {
                        atomicAdd(g_Z + curb * 128 + mbase + mt * 16 + (lane >> 2),     zacc[mt * 2]);
                        atomicAdd(g_Z + curb * 128 + mbase + mt * 16 + (lane >> 2) + 8, zacc[mt * 2 + 1]);
                    }
                }
            }
            #pragma unroll
            for (int nt = 0; nt < 4; nt++)
                #pragma unroll
                for (int q = 0; q < 4; q++) CS[nt][q] = 0.0f;
            zacc[0] = zacc[1] = zacc[2] = zacc[3] = 0.0f;
            curb = b;
        }

        #pragma unroll
        for (int it = 0; it < 8; it++) {
            int idx = tid * 4 + it * 1024;
            int k = idx >> 6, n = idx & 63;
            uint32_t h0, l0, h1, l1;
            bf16_split2(px[it].x, px[it].y, h0, l0);
            bf16_split2(px[it].z, px[it].w, h1, l1);
            uint32_t byte = (uint32_t)(k * 128) + (((uint32_t)(n * 2)) ^ (((uint32_t)k & 7) << 4));
            *(uint2*)(sm + O_XHI + byte) = make_uint2(h0, h1);
            *(uint2*)(sm + O_XLO + byte) = make_uint2(l0, l1);
        }
        if (tile + 1 < hi) {
            int nt2 = tile + 1;
            const float* xb = x + (size_t)(nt2 >> 8) * NCH * NW + (size_t)(nt2 & 255) * 64;
            #pragma unroll
            for (int it = 0; it < 8; it++) {
                int idx = tid * 4 + it * 1024;
                px[it] = *(const float4*)(xb + (size_t)(idx >> 6) * NW + (idx & 63));
            }
        }
        __syncthreads();

        float C[2][8][4];
        #pragma unroll
        for (int i = 0; i < 2; i++)
            #pragma unroll
            for (int j = 0; j < 8; j++)
                #pragma unroll
                for (int q = 0; q < 4; q++) C[i][j][q] = 0.0f;

        #pragma unroll
        for (int ks = 0; ks < 8; ks++) {
            int k0 = ks * 16;
            uint32_t ah[2][4], al[2][4], bh[4][4], bl[4][4];
            #pragma unroll
            for (int mt = 0; mt < 2; mt++) {
                int row = mbase + mt * 16 + (lane & 15);
                uint32_t kb = (uint32_t)((k0 + ((lane >> 4) << 3)) * 2);
                uint32_t off = (uint32_t)(row * 256) + (kb ^ (((uint32_t)row & 7) << 4));
                ldsm_x4(ah[mt], smb + off);
                ldsm_x4(al[mt], smb + 65536u + off);
            }
            #pragma unroll
            for (int t2 = 0; t2 < 4; t2++) {
                int krow = k0 + (lane & 15);
                uint32_t nb = (uint32_t)((t2 * 16 + ((lane >> 4) << 3)) * 2);
                uint32_t off = (uint32_t)(krow * 128) + (nb ^ (((uint32_t)krow & 7) << 4));
                ldsm_x4t(bh[t2], smb + O_XHI + off);
                ldsm_x4t(bl[t2], smb + O_XLO + off);
            }
            #pragma unroll
            for (int mt = 0; mt < 2; mt++)
                #pragma unroll
                for (int t2 = 0; t2 < 4; t2++) {
                    mma16816(C[mt][t2 * 2],     ah[mt], &bh[t2][0]);
                    mma16816(C[mt][t2 * 2 + 1], ah[mt], &bh[t2][2]);
                    mma16816(C[mt][t2 * 2],     ah[mt], &bl[t2][0]);
                    mma16816(C[mt][t2 * 2 + 1], ah[mt], &bl[t2][2]);
                    mma16816(C[mt][t2 * 2],     al[mt], &bh[t2][0]);
                    mma16816(C[mt][t2 * 2 + 1], al[mt], &bh[t2][2]);
                }
        }

        if (wid < 4) {
            float zp[4] = {0.0f, 0.0f, 0.0f, 0.0f};
            #pragma unroll
            for (int mt = 0; mt < 2; mt++) {
                int r0 = mbase + mt * 16 + (lane >> 2);
                int r1 = r0 + 8;
                #pragma unroll
                for (int nt = 0; nt < 8; nt++) {
                    int cc = nt * 8 + 2 * (lane & 3);
                    float e0 = __expf(C[mt][nt][0]);
                    float e1 = __expf(C[mt][nt][1]);
                    float e2 = __expf(C[mt][nt][2]);
                    float e3 = __expf(C[mt][nt][3]);
                    zp[mt * 2]     += e0 + e1;
                    zp[mt * 2 + 1] += e2 + e3;
                    uint32_t hh, ll;
                    bf16_split2(e0, e1, hh, ll);
                    uint32_t byte = (uint32_t)(r0 * 128)
                                  + (((uint32_t)(cc * 2)) ^ (((uint32_t)r0 & 7) << 4));
                    *(uint32_t*)(sm + O_EKH + byte) = hh;
                    *(uint32_t*)(sm + O_EKL + byte) = ll;
                    bf16_split2(e2, e3, hh, ll);
                    byte = (uint32_t)(r1 * 128)
                         + (((uint32_t)(cc * 2)) ^ (((uint32_t)r1 & 7) << 4));
                    *(uint32_t*)(sm + O_EKH + byte) = hh;
                    *(uint32_t*)(sm + O_EKL + byte) = ll;
                }
            }
            #pragma unroll
            for (int i = 0; i < 4; i++) {
                zp[i] += __shfl_xor_sync(0xFFFFFFFFu, zp[i], 1);
                zp[i] += __shfl_xor_sync(0xFFFFFFFFu, zp[i], 2);
                zacc[i] += zp[i];
            }
        } else {
            #pragma unroll
            for (int mt = 0; mt < 2; mt++) {
                int r0 = mbase - 128 + mt * 16 + (lane >> 2);
                int r1 = r0 + 8;
                #pragma unroll
                for (int nt = 0; nt < 8; nt++) {
                    int cc = nt * 8 + 2 * (lane & 3);
                    uint32_t hh, ll;
                    bf16_split2(C[mt][nt][0], C[mt][nt][1], hh, ll);
                    uint32_t byte = (uint32_t)(r0 * 128)
                                  + (((uint32_t)(cc * 2)) ^ (((uint32_t)r0 & 7) << 4));
                    *(uint32_t*)(sm + O_VH + byte) = hh;
                    *(uint32_t*)(sm + O_VL + byte) = ll;
                    bf16_split2(C[mt][nt][2], C[mt][nt][3], hh, ll);
                    byte = (uint32_t)(r1 * 128)
                         + (((uint32_t)(cc * 2)) ^ (((uint32_t)r1 & 7) << 4));
                    *(uint32_t*)(sm + O_VH + byte) = hh;
                    *(uint32_t*)(sm + O_VL + byte) = ll;
                }
            }
        }
        __syncthreads();

        {
            int arow = h * 32 + mh * 16 + (lane & 15);
            uint32_t acol = (uint32_t)((lane >> 4) << 4);
            int erow_in = ((lane >> 4) << 3) + (lane & 7);
            uint32_t bsel = (uint32_t)(((lane >> 3) & 1) << 4);
            #pragma unroll
            for (int ks = 0; ks < 4; ks++) {
                uint32_t kb = (uint32_t)(ks * 32);
                uint32_t aoff = (uint32_t)(arow * 128)
                              + ((kb + acol) ^ (((uint32_t)arow & 7) << 4));
                uint32_t Ah[4], Al[4];
                ldsm_x4(Ah, smb + O_EKH + aoff);
                ldsm_x4(Al, smb + O_EKL + aoff);
                #pragma unroll
                for (int et = 0; et < 2; et++) {
                    int er = h * 32 + et * 16 + erow_in;
                    uint32_t boff = (uint32_t)(er * 128)
                                  + ((kb + bsel) ^ (((uint32_t)er & 7) << 4));
                    uint32_t Bh[4], Bl[4];
                    ldsm_x4(Bh, smb + O_VH + boff);
                    ldsm_x4(Bl, smb + O_VL + boff);
                    mma16816(CS[et * 2],     Ah, &Bh[0]);
                    mma16816(CS[et * 2 + 1], Ah, &Bh[2]);
                    mma16816(CS[et * 2],     Ah, &Bl[0]);
                    mma16816(CS[et * 2 + 1], Ah, &Bl[2]);
                    mma16816(CS[et * 2],     Al, &Bh[0]);
                    mma16816(CS[et * 2 + 1], Al, &Bh[2]);
                }
            }
        }
    }

    if (curb >= 0) {
        float* gS = g_S + curb * 4096 + h * 1024;
        int d0 = mh * 16 + (lane >> 2);
        #pragma unroll
        for (int nt = 0; nt < 4; nt++) {
            int e = nt * 8 + 2 * (lane & 3);
            atomicAdd(gS + d0 * 32 + e,           CS[nt][0]);
            atomicAdd(gS + d0 * 32 + e + 1,       CS[nt][1]);
            atomicAdd(gS + (d0 + 8) * 32 + e,     CS[nt][2]);
            atomicAdd(gS + (d0 + 8) * 32 + e + 1, CS[nt][3]);
        }
        if (wid < 4 && (lane & 3) == 0) {
            #pragma unroll
            for (int mt = 0; mt < 2; mt++) {
                atomicAdd(g_Z + curb * 128 + mbase + mt * 16 + (lane >> 2),     zacc[mt * 2]);
                atomicAdd(g_Z + curb * 128 + mbase + mt * 16 + (lane >> 2) + 8, zacc[mt * 2 + 1]);
            }
        }
    }
}

// ---------------------------------------------------------------------------
__global__ void k_mbuild(const float* __restrict__ Wout) {
    __shared__ float sCtx[4096];
    __shared__ float sWo[16 * 128];
    int b = blockIdx.y, o0 = blockIdx.x * 16;
    int tid = threadIdx.x;
    for (int idx = tid * 4; idx < 4096; idx += 1024) {
        float4 sv = *(const float4*)(g_S + b * 4096 + idx);
        float z = g_Z[b * 128 + (idx >> 5)];
        float r = 1.0f / (z * (float)NW);
        sv.x *= r; sv.y *= r; sv.z *= r; sv.w *= r;
        *(float4*)(sCtx + idx) = sv;
    }
    for (int idx = tid * 4; idx < 2048; idx += 1024)
        *(float4*)(sWo + idx) = *(const float4*)(Wout + (size_t)o0 * 128 + idx);
    __syncthreads();
    for (int idx = tid; idx < 2048; idx += 256) {
        int orr = idx >> 7, hd = idx & 127;
        int hh = hd >> 5, d = hd & 31;
        const float* wrow = sWo + orr * 128 + hh * 32;
        const float* crow = sCtx + hh * 1024 + d * 32;
        float sum = 0.0f;
        #pragma unroll
        for (int e4 = 0; e4 < 8; e4++) {
            float4 w4 = *(const float4*)(wrow + e4 * 4);
            float4 c4 = *(const float4*)(crow + e4 * 4);
            sum += w4.x * c4.x + w4.y * c4.y + w4.z * c4.z + w4.w * c4.w;
        }
        g_M[b * 16384 + (o0 + orr) * 128 + hd] = SCALE_F * sum;
    }
}

// ---------------------------------------------------------------------------
// k_qout, 256 threads, 128-col tiles: warp grid 2x4, each warp 64M x 32N.
// smem: Wq hi 0 / lo 32768; M hi 65536 / lo 98304; x/qsm planes 131072/163840
// (pitch 256B). Total dynamic 196608.
#define QX_HI 131072u
#define QX_LO 163840u

__global__ void __launch_bounds__(256, 1)
k_qout(const float* __restrict__ x, const float* __restrict__ Wqkv,
       const float* __restrict__ b_out, const float* __restrict__ gamma,
       const float* __restrict__ beta, float* __restrict__ out) {
    extern __shared__ char sm[];
    __shared__ float sBias[128], sGamma[128], sBeta[128], sStat[256];
    __shared__ float sPS[256], sPQ[256];
    const uint32_t smb = smem_u32(sm);
    const int tid = threadIdx.x, wid = tid >> 5, lane = tid & 31;
    const int mbase = (wid >> 2) * 64;   // 2 warp-rows of 64 M rows
    const int nbase = (wid & 3) * 32;    // 4 warp-cols of 32 N cols
    const int wrow = wid >> 2;

    w_row_sts(sm, 0u, 32768u, Wqkv, 128, tid, 256);
    if (tid < 128) {
        sBias[tid] = b_out[tid]; sGamma[tid] = gamma[tid]; sBeta[tid] = beta[tid];
    }

    const int NT128 = 2048;   // 16 batches * 128 tiles of 128 cols
    int per = (NT128 + GRID_SM - 1) / GRID_SM;   // 14
    int lo = blockIdx.x * per, hi = min(NT128, lo + per);
    int curb = -1;

    for (int tile = lo; tile < hi; tile++) {
        int b = tile >> 7, n0 = (tile & 127) * 128;
        if (b != curb) {   // safe: prior GEMM2 M-reads were pre-LN-sync
            w_row_sts(sm, 65536u, 98304u, g_M + (size_t)b * 16384, 128, tid, 256);
            curb = b;
        }
        {   // convert x tile (128 rows x 128 cols) to bf16 planes
            const float* xb = x + (size_t)b * NCH * NW + n0;
            #pragma unroll
            for (int it = 0; it < 16; it++) {
                int idx = tid * 4 + it * 1024;
                int k = idx >> 7, n = idx & 127;
                float4 v = *(const float4*)(xb + (size_t)k * NW + n);
                uint32_t h0, l0, h1, l1;
                bf16_split2(v.x, v.y, h0, l0);
                bf16_split2(v.z, v.w, h1, l1);
                uint32_t byte = (uint32_t)(k * 256)
                              + (((uint32_t)(n * 2)) ^ (((uint32_t)k & 7) << 4));
                *(uint2*)(sm + QX_HI + byte) = make_uint2(h0, h1);
                *(uint2*)(sm + QX_LO + byte) = make_uint2(l0, l1);
            }
        }
        __syncthreads();

        float C[4][4][4];
        #define DO_GEMM(ABASE0)                                                          \
        do {                                                                             \
            _Pragma("unroll")                                                            \
            for (int i = 0; i < 4; i++)                                                  \
                _Pragma("unroll")                                                        \
                for (int j = 0; j < 4; j++)                                              \
                    _Pragma("unroll")                                                    \
                    for (int q = 0; q < 4; q++) C[i][j][q] = 0.0f;                       \
            _Pragma("unroll")                                                            \
            for (int ks = 0; ks < 8; ks++) {                                             \
                int k0 = ks * 16;                                                        \
                uint32_t ah[4][4], al[4][4], bh[2][4], bl[2][4];                         \
                _Pragma("unroll")                                                        \
                for (int mt = 0; mt < 4; mt++) {                                         \
                    int row = mbase + mt * 16 + (lane & 15);                             \
                    uint32_t kb = (uint32_t)((k0 + ((lane >> 4) << 3)) * 2);             \
                    uint32_t off = (uint32_t)(row * 256)                                 \
                                 + (kb ^ (((uint32_t)row & 7) << 4));                    \
                    ldsm_x4(ah[mt], smb + (ABASE0) + off);                               \
                    ldsm_x4(al[mt], smb + (ABASE0) + 32768u + off);                      \
                }                                                                        \
                _Pragma("unroll")                                                        \
                for (int t2 = 0; t2 < 2; t2++) {                                         \
                    int krow = k0 + (lane & 15);                                         \
                    uint32_t nb = (uint32_t)((nbase + t2 * 16 + ((lane >> 4) << 3)) * 2);\
                    uint32_t off = (uint32_t)(krow * 256)                                \
                                 + (nb ^ (((uint32_t)krow & 7) << 4));                   \
                    ldsm_x4t(bh[t2], smb + QX_HI + off);                                 \
                    ldsm_x4t(bl[t2], smb + QX_LO + off);                                 \
                }                                                                        \
                _Pragma("unroll")                                                        \
                for (int mt = 0; mt < 4; mt++)                                           \
                    _Pragma("unroll")                                                    \
                    for (int t2 = 0; t2 < 2; t2++) {                                     \
                        mma16816(C[mt][t2 * 2],     ah[mt], &bh[t2][0]);                 \
                        mma16816(C[mt][t2 * 2 + 1], ah[mt], &bh[t2][2]);                 \
                        mma16816(C[mt][t2 * 2],     ah[mt], &bl[t2][0]);                 \
                        mma16816(C[mt][t2 * 2 + 1], ah[mt], &bl[t2][2]);                 \
                        mma16816(C[mt][t2 * 2],     al[mt], &bh[t2][0]);                 \
                        mma16816(C[mt][t2 * 2 + 1], al[mt], &bh[t2][2]);                 \
                    }                                                                    \
            }                                                                            \
        } while (0)

        DO_GEMM(0u);       // q = W_q @ x
        __syncthreads();   // x-plane reads done before qsm overwrite

        {   // softmax over head-dim: rows mbase..+63 = heads {mt0,1} and {mt2,3}
            #pragma unroll
            for (int hp = 0; hp < 2; hp++)
                #pragma unroll
                for (int nt = 0; nt < 4; nt++) {
                    float p0 = 0.0f, p1 = 0.0f;
                    #pragma unroll
                    for (int m2 = 0; m2 < 2; m2++) {
                        int mt = hp * 2 + m2;
                        #pragma unroll
                        for (int q = 0; q < 4; q++) C[mt][nt][q] = __expf(C[mt][nt][q]);
                        p0 += C[mt][nt][0] + C[mt][nt][2];
                        p1 += C[mt][nt][1] + C[mt][nt][3];
                    }
                    p0 += __shfl_xor_sync(0xFFFFFFFFu, p0, 4);
                    p0 += __shfl_xor_sync(0xFFFFFFFFu, p0, 8);
                    p0 += __shfl_xor_sync(0xFFFFFFFFu, p0, 16);
                    p1 += __shfl_xor_sync(0xFFFFFFFFu, p1, 4);
                    p1 += __shfl_xor_sync(0xFFFFFFFFu, p1, 8);
                    p1 += __shfl_xor_sync(0xFFFFFFFFu, p1, 16);
                    float r0 = __fdividef(1.0f, p0), r1 = __fdividef(1.0f, p1);
                    #pragma unroll
                    for (int m2 = 0; m2 < 2; m2++) {
                        int mt = hp * 2 + m2;
                        C[mt][nt][0] *= r0; C[mt][nt][2] *= r0;
                        C[mt][nt][1] *= r1; C[mt][nt][3] *= r1;
                    }
                }
            #pragma unroll
            for (int mt = 0; mt < 4; mt++)
                #pragma unroll
                for (int nt = 0; nt < 4; nt++) {
                    int r0 = mbase + mt * 16 + (lane >> 2);
                    int cc = nbase + nt * 8 + 2 * (lane & 3);
                    uint32_t hh, ll;
                    bf16_split2(C[mt][nt][0], C[mt][nt][1], hh, ll);
                    uint32_t byte = (uint32_t)(r0 * 256)
                                  + (((uint32_t)(cc * 2)) ^ (((uint32_t)r0 & 7) << 4));
                    *(uint32_t*)(sm + QX_HI + byte) = hh;
                    *(uint32_t*)(sm + QX_LO + byte) = ll;
                    int r1 = r0 + 8;
                    bf16_split2(C[mt][nt][2], C[mt][nt][3], hh, ll);
                    byte = (uint32_t)(r1 * 256)
                         + (((uint32_t)(cc * 2)) ^ (((uint32_t)r1 & 7) << 4));
                    *(uint32_t*)(sm + QX_HI + byte) = hh;
                    *(uint32_t*)(sm + QX_LO + byte) = ll;
                }
        }
        __syncthreads();

        DO_GEMM(65536u);   // y = M_b @ qsm
        #undef DO_GEMM

        {   // bias + LN column partials from fragments (this warp-row's 64 rows)
            float ps[4][2], pq[4][2];
            #pragma unroll
            for (int nt = 0; nt < 4; nt++) { ps[nt][0] = ps[nt][1] = pq[nt][0] = pq[nt][1] = 0.0f; }
            #pragma unroll
            for (int mt = 0; mt < 4; mt++) {
                int r0 = mbase + mt * 16 + (lane >> 2);
                float b0 = sBias[r0], b1 = sBias[r0 + 8];
                #pragma unroll
                for (int nt = 0; nt < 4; nt++) {
                    C[mt][nt][0] += b0; C[mt][nt][1] += b0;
                    C[mt][nt][2] += b1; C[mt][nt][3] += b1;
                    ps[nt][0] += C[mt][nt][0] + C[mt][nt][2];
                    ps[nt][1] += C[mt][nt][1] + C[mt][nt][3];
                    pq[nt][0] += C[mt][nt][0] * C[mt][nt][0] + C[mt][nt][2] * C[mt][nt][2];
                    pq[nt][1] += C[mt][nt][1] * C[mt][nt][1] + C[mt][nt][3] * C[mt][nt][3];
                }
            }
            #pragma unroll
            for (int nt = 0; nt < 4; nt++)
                #pragma unroll
                for (int cp = 0; cp < 2; cp++) {
                    ps[nt][cp] += __shfl_xor_sync(0xFFFFFFFFu, ps[nt][cp], 4);
                    ps[nt][cp] += __shfl_xor_sync(0xFFFFFFFFu, ps[nt][cp], 8);
                    ps[nt][cp] += __shfl_xor_sync(0xFFFFFFFFu, ps[nt][cp], 16);
                    pq[nt][cp] += __shfl_xor_sync(0xFFFFFFFFu, pq[nt][cp], 4);
                    pq[nt][cp] += __shfl_xor_sync(0xFFFFFFFFu, pq[nt][cp], 8);
                    pq[nt][cp] += __shfl_xor_sync(0xFFFFFFFFu, pq[nt][cp], 16);
                }
            if (lane < 4) {
                #pragma unroll
                for (int nt = 0; nt < 4; nt++) {
                    int cc = nbase + nt * 8 + 2 * lane;
                    sPS[wrow * 128 + cc]     = ps[nt][0];
                    sPS[wrow * 128 + cc + 1] = ps[nt][1];
                    sPQ[wrow * 128 + cc]     = pq[nt][0];
                    sPQ[wrow * 128 + cc + 1] = pq[nt][1];
                }
            }
        }
        __syncthreads();
        if (tid < 128) {
            float s  = sPS[tid] + sPS[128 + tid];
            float sq = sPQ[tid] + sPQ[128 + tid];
            float mean = s * (1.0f / 128.0f);
            float var = sq * (1.0f / 128.0f) - mean * mean;
            sStat[tid * 2] = mean;
            sStat[tid * 2 + 1] = rsqrtf(var + LN_EPS);
        }
        __syncthreads();

        {   // apply LN from fragments, store to global
            float* ob = out + (size_t)b * NCH * NW + n0;
            #pragma unroll
            for (int mt = 0; mt < 4; mt++) {
                int r0 = mbase + mt * 16 + (lane >> 2);
                int r1 = r0 + 8;
                float g0 = sGamma[r0], be0 = sBeta[r0];
                float g1 = sGamma[r1], be1 = sBeta[r1];
                #pragma unroll
                for (int nt = 0; nt < 4; nt++) {
                    int cc = nbase + nt * 8 + 2 * (lane & 3);
                    float m0 = sStat[2 * cc],       rs0 = sStat[2 * cc + 1];
                    float m1 = sStat[2 * (cc + 1)], rs1 = sStat[2 * (cc + 1) + 1];
                    *(float2*)(ob + (size_t)r0 * NW + cc) = make_float2(
                        (C[mt][nt][0] - m0) * rs0 * g0 + be0,
                        (C[mt][nt][1] - m1) * rs1 * g0 + be0);
                    *(float2*)(ob + (size_t)r1 * NW + cc) = make_float2(
                        (C[mt][nt][2] - m0) * rs0 * g1 + be1,
                        (C[mt][nt][3] - m1) * rs1 * g1 + be1);
                }
            }
        }
    }
}

// ---------------------------------------------------------------------------
extern "C" void kernel_launch(void* const* d_in, const int* in_sizes, int n_in,
                              void* d_out, int out_size) {
    const float* x    = (const float*)d_in[0];
    const float* Wqkv = (const float*)d_in[1];
    const float* Wout = (const float*)d_in[2];
    const float* bo   = (const float*)d_in[3];
    const float* gm   = (const float*)d_in[4];
    const float* bt   = (const float*)d_in[5];
    float* out = (float*)d_out;

    const int SMEM_A = 229376;
    const int SMEM_C = 196608;
    cudaFuncSetAttribute(k_kvctx, cudaFuncAttributeMaxDynamicSharedMemorySize, SMEM_A);
    cudaFuncSetAttribute(k_qout,  cudaFuncAttributeMaxDynamicSharedMemorySize, SMEM_C);

    k_zero<<<66, 1024>>>();
    k_kvctx<<<GRID_SM, 256, SMEM_A>>>(x, Wqkv);
    k_mbuild<<<dim3(8, 16), 256>>>(Wout);
    k_qout<<<GRID_SM, 256, SMEM_C>>>(x, Wqkv, bo, gm, bt, out);
}

// round 13
// speedup vs baseline: 1.4894x; 1.4894x over previous
#include <cuda_runtime.h>
#include <cstdint>

#define NB 16
#define NCH 128
#define NW 16384
#define NTILES 4096
#define GRID_SM 152
#define SCALE_F 0.17677669529663687f
#define LN_EPS 1e-5f

__device__ float g_S[NB * 4096];
__device__ float g_Z[NB * 128];
__device__ float g_M[NB * 128 * 128];

__device__ __forceinline__ uint32_t smem_u32(const void* p) {
    uint32_t a;
    asm("{ .reg .u64 t; cvta.to.shared.u64 t, %1; cvt.u32.u64 %0, t; }" : "=r"(a) : "l"(p));
    return a;
}
__device__ __forceinline__ void bf16_split2(float a, float b, uint32_t& h, uint32_t& l) {
    asm("cvt.rn.bf16x2.f32 %0, %1, %2;" : "=r"(h) : "f"(b), "f"(a));
    float ra = a - __uint_as_float(h << 16);
    float rb = b - __uint_as_float(h & 0xFFFF0000u);
    asm("cvt.rn.bf16x2.f32 %0, %1, %2;" : "=r"(l) : "f"(rb), "f"(ra));
}
__device__ __forceinline__ void ldsm_x4(uint32_t* a, uint32_t addr) {
    asm volatile("ldmatrix.sync.aligned.m8n8.x4.shared.b16 {%0,%1,%2,%3}, [%4];"
                 : "=r"(a[0]), "=r"(a[1]), "=r"(a[2]), "=r"(a[3]) : "r"(addr));
}
__device__ __forceinline__ void ldsm_x4t(uint32_t* a, uint32_t addr) {
    asm volatile("ldmatrix.sync.aligned.m8n8.x4.trans.shared.b16 {%0,%1,%2,%3}, [%4];"
                 : "=r"(a[0]), "=r"(a[1]), "=r"(a[2]), "=r"(a[3]) : "r"(addr));
}
__device__ __forceinline__ void mma16816(float* c, const uint32_t* a, const uint32_t* b) {
    asm volatile("mma.sync.aligned.m16n8k16.row.col.f32.bf16.bf16.f32 "
                 "{%0,%1,%2,%3},{%4,%5,%6,%7},{%8,%9},{%0,%1,%2,%3};"
                 : "+f"(c[0]), "+f"(c[1]), "+f"(c[2]), "+f"(c[3])
                 : "r"(a[0]), "r"(a[1]), "r"(a[2]), "r"(a[3]), "r"(b[0]), "r"(b[1]));
}

// fp32 rows of 128 -> two bf16 planes in smem, rows of 256B, XOR-16B swizzle
__device__ __forceinline__ void w_row_sts(char* sm, uint32_t oh, uint32_t ol,
                                          const float* __restrict__ src,
                                          int nrows, int tid, int nthreads) {
    for (int idx = tid * 4; idx < nrows * 128; idx += nthreads * 4) {
        int m = idx >> 7, k = idx & 127;
        float4 w = *(const float4*)(src + m * 128 + k);
        uint32_t h0, l0, h1, l1;
        bf16_split2(w.x, w.y, h0, l0);
        bf16_split2(w.z, w.w, h1, l1);
        uint32_t byte = (uint32_t)(m * 256) + (((uint32_t)(k * 2)) ^ (((uint32_t)m & 7) << 4));
        *(uint2*)(sm + oh + byte) = make_uint2(h0, h1);
        *(uint2*)(sm + ol + byte) = make_uint2(l0, l1);
    }
}

// ---------------------------------------------------------------------------
__global__ void k_zero() {
    int i = blockIdx.x * blockDim.x + threadIdx.x;
    if (i < NB * 4096) g_S[i] = 0.0f;
    else g_Z[i - NB * 4096] = 0.0f;
}

// ---------------------------------------------------------------------------
// k_kvctx: UNCHANGED from R10 (passing, 331.3us total)
#define O_XHI 131072u
#define O_XLO 147456u
#define O_EKH 163840u
#define O_EKL 180224u
#define O_VH  196608u
#define O_VL  212992u

__global__ void __launch_bounds__(256, 1)
k_kvctx(const float* __restrict__ x, const float* __restrict__ Wqkv) {
    extern __shared__ char sm[];
    const uint32_t smb = smem_u32(sm);
    const int tid = threadIdx.x, wid = tid >> 5, lane = tid & 31;
    const int mbase = wid * 32;
    const int h = wid >> 1, mh = wid & 1;

    w_row_sts(sm, 0u, 65536u, Wqkv + 128 * 128, 256, tid, 256);

    int per = (NTILES + GRID_SM - 1) / GRID_SM;   // 27
    int lo = blockIdx.x * per, hi = min(NTILES, lo + per);

    float CS[4][4];
    float zacc[4];
    int curb = -1;

    float4 px[8];
    if (lo < hi) {
        const float* xb = x + (size_t)(lo >> 8) * NCH * NW + (size_t)(lo & 255) * 64;
        #pragma unroll
        for (int it = 0; it < 8; it++) {
            int idx = tid * 4 + it * 1024;
            px[it] = *(const float4*)(xb + (size_t)(idx >> 6) * NW + (idx & 63));
        }
    }

    for (int tile = lo; tile < hi; tile++) {
        int b = tile >> 8;
        if (b != curb) {
            if (curb >= 0) {
                float* gS = g_S + curb * 4096 + h * 1024;
                int d0 = mh * 16 + (lane >> 2);
                #pragma unroll
                for (int nt = 0; nt < 4; nt++) {
                    int e = nt * 8 + 2 * (lane & 3);
                    atomicAdd(gS + d0 * 32 + e,           CS[nt][0]);
                    atomicAdd(gS + d0 * 32 + e + 1,       CS[nt][1]);
                    atomicAdd(gS + (d0 + 8) * 32 + e,     CS[nt][2]);
                    atomicAdd(gS + (d0 + 8) * 32 + e + 1, CS[nt][3]);
                }
                if (wid < 4 && (lane & 3) == 0) {
                    #pragma unroll
                    for (int mt = 0; mt < 2; mt++) {
                        atomicAdd(g_Z + curb * 128 + mbase + mt * 16 + (lane >> 2),     zacc[mt * 2]);
                        atomicAdd(g_Z + curb * 128 + mbase + mt * 16 + (lane >> 2) + 8, zacc[mt * 2 + 1]);
                    }
                }
            }
            #pragma unroll
            for (int nt = 0; nt < 4; nt++)
                #pragma unroll
                for (int q = 0; q < 4; q++) CS[nt][q] = 0.0f;
            zacc[0] = zacc[1] = zacc[2] = zacc[3] = 0.0f;
            curb = b;
        }

        #pragma unroll
        for (int it = 0; it < 8; it++) {
            int idx = tid * 4 + it * 1024;
            int k = idx >> 6, n = idx & 63;
            uint32_t h0, l0, h1, l1;
            bf16_split2(px[it].x, px[it].y, h0, l0);
            bf16_split2(px[it].z, px[it].w, h1, l1);
            uint32_t byte = (uint32_t)(k * 128) + (((uint32_t)(n * 2)) ^ (((uint32_t)k & 7) << 4));
            *(uint2*)(sm + O_XHI + byte) = make_uint2(h0, h1);
            *(uint2*)(sm + O_XLO + byte) = make_uint2(l0, l1);
        }
        if (tile + 1 < hi) {
            int nt2 = tile + 1;
            const float* xb = x + (size_t)(nt2 >> 8) * NCH * NW + (size_t)(nt2 & 255) * 64;
            #pragma unroll
            for (int it = 0; it < 8; it++) {
                int idx = tid * 4 + it * 1024;
                px[it] = *(const float4*)(xb + (size_t)(idx >> 6) * NW + (idx & 63));
            }
        }
        __syncthreads();

        float C[2][8][4];
        #pragma unroll
        for (int i = 0; i < 2; i++)
            #pragma unroll
            for (int j = 0; j < 8; j++)
                #pragma unroll
                for (int q = 0; q < 4; q++) C[i][j][q] = 0.0f;

        #pragma unroll
        for (int ks = 0; ks < 8; ks++) {
            int k0 = ks * 16;
            uint32_t ah[2][4], al[2][4], bh[4][4], bl[4][4];
            #pragma unroll
            for (int mt = 0; mt < 2; mt++) {
                int row = mbase + mt * 16 + (lane & 15);
                uint32_t kb = (uint32_t)((k0 + ((lane >> 4) << 3)) * 2);
                uint32_t off = (uint32_t)(row * 256) + (kb ^ (((uint32_t)row & 7) << 4));
                ldsm_x4(ah[mt], smb + off);
                ldsm_x4(al[mt], smb + 65536u + off);
            }
            #pragma unroll
            for (int t2 = 0; t2 < 4; t2++) {
                int krow = k0 + (lane & 15);
                uint32_t nb = (uint32_t)((t2 * 16 + ((lane >> 4) << 3)) * 2);
                uint32_t off = (uint32_t)(krow * 128) + (nb ^ (((uint32_t)krow & 7) << 4));
                ldsm_x4t(bh[t2], smb + O_XHI + off);
                ldsm_x4t(bl[t2], smb + O_XLO + off);
            }
            #pragma unroll
            for (int mt = 0; mt < 2; mt++)
                #pragma unroll
                for (int t2 = 0; t2 < 4; t2++) {
                    mma16816(C[mt][t2 * 2],     ah[mt], &bh[t2][0]);
                    mma16816(C[mt][t2 * 2 + 1], ah[mt], &bh[t2][2]);
                    mma16816(C[mt][t2 * 2],     ah[mt], &bl[t2][0]);
                    mma16816(C[mt][t2 * 2 + 1], ah[mt], &bl[t2][2]);
                    mma16816(C[mt][t2 * 2],     al[mt], &bh[t2][0]);
                    mma16816(C[mt][t2 * 2 + 1], al[mt], &bh[t2][2]);
                }
        }

        if (wid < 4) {
            float zp[4] = {0.0f, 0.0f, 0.0f, 0.0f};
            #pragma unroll
            for (int mt = 0; mt < 2; mt++) {
                int r0 = mbase + mt * 16 + (lane >> 2);
                int r1 = r0 + 8;
                #pragma unroll
                for (int nt = 0; nt < 8; nt++) {
                    int cc = nt * 8 + 2 * (lane & 3);
                    float e0 = __expf(C[mt][nt][0]);
                    float e1 = __expf(C[mt][nt][1]);
                    float e2 = __expf(C[mt][nt][2]);
                    float e3 = __expf(C[mt][nt][3]);
                    zp[mt * 2]     += e0 + e1;
                    zp[mt * 2 + 1] += e2 + e3;
                    uint32_t hh, ll;
                    bf16_split2(e0, e1, hh, ll);
                    uint32_t byte = (uint32_t)(r0 * 128)
                                  + (((uint32_t)(cc * 2)) ^ (((uint32_t)r0 & 7) << 4));
                    *(uint32_t*)(sm + O_EKH + byte) = hh;
                    *(uint32_t*)(sm + O_EKL + byte) = ll;
                    bf16_split2(e2, e3, hh, ll);
                    byte = (uint32_t)(r1 * 128)
                         + (((uint32_t)(cc * 2)) ^ (((uint32_t)r1 & 7) << 4));
                    *(uint32_t*)(sm + O_EKH + byte) = hh;
                    *(uint32_t*)(sm + O_EKL + byte) = ll;
                }
            }
            #pragma unroll
            for (int i = 0; i < 4; i++) {
                zp[i] += __shfl_xor_sync(0xFFFFFFFFu, zp[i], 1);
                zp[i] += __shfl_xor_sync(0xFFFFFFFFu, zp[i], 2);
                zacc[i] += zp[i];
            }
        } else {
            #pragma unroll
            for (int mt = 0; mt < 2; mt++) {
                int r0 = mbase - 128 + mt * 16 + (lane >> 2);
                int r1 = r0 + 8;
                #pragma unroll
                for (int nt = 0; nt < 8; nt++) {
                    int cc = nt * 8 + 2 * (lane & 3);
                    uint32_t hh, ll;
                    bf16_split2(C[mt][nt][0], C[mt][nt][1], hh, ll);
                    uint32_t byte = (uint32_t)(r0 * 128)
                                  + (((uint32_t)(cc * 2)) ^ (((uint32_t)r0 & 7) << 4));
                    *(uint32_t*)(sm + O_VH + byte) = hh;
                    *(uint32_t*)(sm + O_VL + byte) = ll;
                    bf16_split2(C[mt][nt][2], C[mt][nt][3], hh, ll);
                    byte = (uint32_t)(r1 * 128)
                         + (((uint32_t)(cc * 2)) ^ (((uint32_t)r1 & 7) << 4));
                    *(uint32_t*)(sm + O_VH + byte) = hh;
                    *(uint32_t*)(sm + O_VL + byte) = ll;
                }
            }
        }
        __syncthreads();

        {
            int arow = h * 32 + mh * 16 + (lane & 15);
            uint32_t acol = (uint32_t)((lane >> 4) << 4);
            int erow_in = ((lane >> 4) << 3) + (lane & 7);
            uint32_t bsel = (uint32_t)(((lane >> 3) & 1) << 4);
            #pragma unroll
            for (int ks = 0; ks < 4; ks++) {
                uint32_t kb = (uint32_t)(ks * 32);
                uint32_t aoff = (uint32_t)(arow * 128)
                              + ((kb + acol) ^ (((uint32_t)arow & 7) << 4));
                uint32_t Ah[4], Al[4];
                ldsm_x4(Ah, smb + O_EKH + aoff);
                ldsm_x4(Al, smb + O_EKL + aoff);
                #pragma unroll
                for (int et = 0; et < 2; et++) {
                    int er = h * 32 + et * 16 + erow_in;
                    uint32_t boff = (uint32_t)(er * 128)
                                  + ((kb + bsel) ^ (((uint32_t)er & 7) << 4));
                    uint32_t Bh[4], Bl[4];
                    ldsm_x4(Bh, smb + O_VH + boff);
                    ldsm_x4(Bl, smb + O_VL + boff);
                    mma16816(CS[et * 2],     Ah, &Bh[0]);
                    mma16816(CS[et * 2 + 1], Ah, &Bh[2]);
                    mma16816(CS[et * 2],     Ah, &Bl[0]);
                    mma16816(CS[et * 2 + 1], Ah, &Bl[2]);
                    mma16816(CS[et * 2],     Al, &Bh[0]);
                    mma16816(CS[et * 2 + 1], Al, &Bh[2]);
                }
            }
        }
    }

    if (curb >= 0) {
        float* gS = g_S + curb * 4096 + h * 1024;
        int d0 = mh * 16 + (lane >> 2);
        #pragma unroll
        for (int nt = 0; nt < 4; nt++) {
            int e = nt * 8 + 2 * (lane & 3);
            atomicAdd(gS + d0 * 32 + e,           CS[nt][0]);
            atomicAdd(gS + d0 * 32 + e + 1,       CS[nt][1]);
            atomicAdd(gS + (d0 + 8) * 32 + e,     CS[nt][2]);
            atomicAdd(gS + (d0 + 8) * 32 + e + 1, CS[nt][3]);
        }
        if (wid < 4 && (lane & 3) == 0) {
            #pragma unroll
            for (int mt = 0; mt < 2; mt++) {
                atomicAdd(g_Z + curb * 128 + mbase + mt * 16 + (lane >> 2),     zacc[mt * 2]);
                atomicAdd(g_Z + curb * 128 + mbase + mt * 16 + (lane >> 2) + 8, zacc[mt * 2 + 1]);
            }
        }
    }
}

// ---------------------------------------------------------------------------
__global__ void k_mbuild(const float* __restrict__ Wout) {
    __shared__ float sCtx[4096];
    __shared__ float sWo[16 * 128];
    int b = blockIdx.y, o0 = blockIdx.x * 16;
    int tid = threadIdx.x;
    for (int idx = tid * 4; idx < 4096; idx += 1024) {
        float4 sv = *(const float4*)(g_S + b * 4096 + idx);
        float z = g_Z[b * 128 + (idx >> 5)];
        float r = 1.0f / (z * (float)NW);
        sv.x *= r; sv.y *= r; sv.z *= r; sv.w *= r;
        *(float4*)(sCtx + idx) = sv;
    }
    for (int idx = tid * 4; idx < 2048; idx += 1024)
        *(float4*)(sWo + idx) = *(const float4*)(Wout + (size_t)o0 * 128 + idx);
    __syncthreads();
    for (int idx = tid; idx < 2048; idx += 256) {
        int orr = idx >> 7, hd = idx & 127;
        int hh = hd >> 5, d = hd & 31;
        const float* wrow = sWo + orr * 128 + hh * 32;
        const float* crow = sCtx + hh * 1024 + d * 32;
        float sum = 0.0f;
        #pragma unroll
        for (int e4 = 0; e4 < 8; e4++) {
            float4 w4 = *(const float4*)(wrow + e4 * 4);
            float4 c4 = *(const float4*)(crow + e4 * 4);
            sum += w4.x * c4.x + w4.y * c4.y + w4.z * c4.z + w4.w * c4.w;
        }
        g_M[b * 16384 + (o0 + orr) * 128 + hd] = SCALE_F * sum;
    }
}

// ---------------------------------------------------------------------------
// k_qout, 512 threads, 128-col x-tiles: warp grid 4x4, each warp 32M x 32N.
// smem: Wq hi 0 / lo 32768; M hi 65536 / lo 98304; x/qsm planes 131072/163840
// (pitch 256B). Total dynamic 196608.
#define QX_HI 131072u
#define QX_LO 163840u

__global__ void __launch_bounds__(512, 1)
k_qout(const float* __restrict__ x, const float* __restrict__ Wqkv,
       const float* __restrict__ b_out, const float* __restrict__ gamma,
       const float* __restrict__ beta, float* __restrict__ out) {
    extern __shared__ char sm[];
    __shared__ float sBias[128], sGamma[128], sBeta[128], sStat[256];
    __shared__ float sPS[512], sPQ[512];
    const uint32_t smb = smem_u32(sm);
    const int tid = threadIdx.x, wid = tid >> 5, lane = tid & 31;
    const int mbase = (wid >> 2) * 32;   // 4 warp-rows of 32 M rows (= 1 head)
    const int nbase = (wid & 3) * 32;    // 4 warp-cols of 32 N cols
    const int wrow = wid >> 2;

    w_row_sts(sm, 0u, 32768u, Wqkv, 128, tid, 512);
    if (tid < 128) {
        sBias[tid] = b_out[tid]; sGamma[tid] = gamma[tid]; sBeta[tid] = beta[tid];
    }

    const int NT128 = 2048;   // 16 batches * 128 tiles of 128 cols
    int per = (NT128 + GRID_SM - 1) / GRID_SM;   // 14
    int lo = blockIdx.x * per, hi = min(NT128, lo + per);
    int curb = -1;

    for (int tile = lo; tile < hi; tile++) {
        int b = tile >> 7, n0 = (tile & 127) * 128;
        if (b != curb) {   // safe: prior tile's M reads complete before LN sync
            w_row_sts(sm, 65536u, 98304u, g_M + (size_t)b * 16384, 128, tid, 512);
            curb = b;
        }
        {   // convert x tile (128 rows x 128 cols) to bf16 planes, pitch 256B
            const float* xb = x + (size_t)b * NCH * NW + n0;
            #pragma unroll
            for (int it = 0; it < 8; it++) {
                int idx = tid * 4 + it * 2048;
                int k = idx >> 7, n = idx & 127;
                float4 v = *(const float4*)(xb + (size_t)k * NW + n);
                uint32_t h0, l0, h1, l1;
                bf16_split2(v.x, v.y, h0, l0);
                bf16_split2(v.z, v.w, h1, l1);
                uint32_t byte = (uint32_t)(k * 256)
                              + (((uint32_t)(n * 2)) ^ (((uint32_t)k & 7) << 4));
                *(uint2*)(sm + QX_HI + byte) = make_uint2(h0, h1);
                *(uint2*)(sm + QX_LO + byte) = make_uint2(l0, l1);
            }
        }
        __syncthreads();

        float C[2][4][4];
        #define DO_GEMM(ABASE0)                                                          \
        do {                                                                             \
            _Pragma("unroll")                                                            \
            for (int i = 0; i < 2; i++)                                                  \
                _Pragma("unroll")                                                        \
                for (int j = 0; j < 4; j++)                                              \
                    _Pragma("unroll")                                                    \
                    for (int q = 0; q < 4; q++) C[i][j][q] = 0.0f;                       \
            _Pragma("unroll")                                                            \
            for (int ks = 0; ks < 8; ks++) {                                             \
                int k0 = ks * 16;                                                        \
                uint32_t ah[2][4], al[2][4];                                             \
                _Pragma("unroll")                                                        \
                for (int mt = 0; mt < 2; mt++) {                                         \
                    int row = mbase + mt * 16 + (lane & 15);                             \
                    uint32_t kb = (uint32_t)((k0 + ((lane >> 4) << 3)) * 2);             \
                    uint32_t off = (uint32_t)(row * 256)                                 \
                                 + (kb ^ (((uint32_t)row & 7) << 4));                    \
                    ldsm_x4(ah[mt], smb + (ABASE0) + off);                               \
                    ldsm_x4(al[mt], smb + (ABASE0) + 32768u + off);                      \
                }                                                                        \
                _Pragma("unroll")                                                        \
                for (int t2 = 0; t2 < 2; t2++) {                                         \
                    uint32_t bh[4], bl[4];                                               \
                    int krow = k0 + (lane & 15);                                         \
                    uint32_t nb = (uint32_t)((nbase + t2 * 16 + ((lane >> 4) << 3)) * 2);\
                    uint32_t off = (uint32_t)(krow * 256)                                \
                                 + (nb ^ (((uint32_t)krow & 7) << 4));                   \
                    ldsm_x4t(bh, smb + QX_HI + off);                                     \
                    ldsm_x4t(bl, smb + QX_LO + off);                                     \
                    _Pragma("unroll")                                                    \
                    for (int mt = 0; mt < 2; mt++) {                                     \
                        mma16816(C[mt][t2 * 2],     ah[mt], &bh[0]);                     \
                        mma16816(C[mt][t2 * 2 + 1], ah[mt], &bh[2]);                     \
                        mma16816(C[mt][t2 * 2],     ah[mt], &bl[0]);                     \
                        mma16816(C[mt][t2 * 2 + 1], ah[mt], &bl[2]);                     \
                        mma16816(C[mt][t2 * 2],     al[mt], &bh[0]);                     \
                        mma16816(C[mt][t2 * 2 + 1], al[mt], &bh[2]);                     \
                    }                                                                    \
                }                                                                        \
            }                                                                            \
        } while (0)

        DO_GEMM(0u);       // q = W_q @ x
        __syncthreads();   // x-plane reads done before qsm overwrite

        {   // softmax over head-dim (warp-row = one head of 32 rows)
            #pragma unroll
            for (int nt = 0; nt < 4; nt++) {
                float p0 = 0.0f, p1 = 0.0f;
                #pragma unroll
                for (int mt = 0; mt < 2; mt++) {
                    #pragma unroll
                    for (int q = 0; q < 4; q++) C[mt][nt][q] = __expf(C[mt][nt][q]);
                    p0 += C[mt][nt][0] + C[mt][nt][2];
                    p1 += C[mt][nt][1] + C[mt][nt][3];
                }
                p0 += __shfl_xor_sync(0xFFFFFFFFu, p0, 4);
                p0 += __shfl_xor_sync(0xFFFFFFFFu, p0, 8);
                p0 += __shfl_xor_sync(0xFFFFFFFFu, p0, 16);
                p1 += __shfl_xor_sync(0xFFFFFFFFu, p1, 4);
                p1 += __shfl_xor_sync(0xFFFFFFFFu, p1, 8);
                p1 += __shfl_xor_sync(0xFFFFFFFFu, p1, 16);
                float r0 = __fdividef(1.0f, p0), r1 = __fdividef(1.0f, p1);
                #pragma unroll
                for (int mt = 0; mt < 2; mt++) {
                    C[mt][nt][0] *= r0; C[mt][nt][2] *= r0;
                    C[mt][nt][1] *= r1; C[mt][nt][3] *= r1;
                }
            }
            #pragma unroll
            for (int mt = 0; mt < 2; mt++)
                #pragma unroll
                for (int nt = 0; nt < 4; nt++) {
                    int r0 = mbase + mt * 16 + (lane >> 2);
                    int cc = nbase + nt * 8 + 2 * (lane & 3);
                    uint32_t hh, ll;
                    bf16_split2(C[mt][nt][0], C[mt][nt][1], hh, ll);
                    uint32_t byte = (uint32_t)(r0 * 256)
                                  + (((uint32_t)(cc * 2)) ^ (((uint32_t)r0 & 7) << 4));
                    *(uint32_t*)(sm + QX_HI + byte) = hh;
                    *(uint32_t*)(sm + QX_LO + byte) = ll;
                    int r1 = r0 + 8;
                    bf16_split2(C[mt][nt][2], C[mt][nt][3], hh, ll);
                    byte = (uint32_t)(r1 * 256)
                         + (((uint32_t)(cc * 2)) ^ (((uint32_t)r1 & 7) << 4));
                    *(uint32_t*)(sm + QX_HI + byte) = hh;
                    *(uint32_t*)(sm + QX_LO + byte) = ll;
                }
        }
        __syncthreads();

        DO_GEMM(65536u);   // y = M_b @ qsm
        #undef DO_GEMM

        {   // bias + LN column partials from fragments
            float ps[4][2], pq[4][2];
            #pragma unroll
            for (int nt = 0; nt < 4; nt++) { ps[nt][0] = ps[nt][1] = pq[nt][0] = pq[nt][1] = 0.0f; }
            #pragma unroll
            for (int mt = 0; mt < 2; mt++) {
                int r0 = mbase + mt * 16 + (lane >> 2);
                float b0 = sBias[r0], b1 = sBias[r0 + 8];
                #pragma unroll
                for (int nt = 0; nt < 4; nt++) {
                    C[mt][nt][0] += b0; C[mt][nt][1] += b0;
                    C[mt][nt][2] += b1; C[mt][nt][3] += b1;
                    ps[nt][0] += C[mt][nt][0] + C[mt][nt][2];
                    ps[nt][1] += C[mt][nt][1] + C[mt][nt][3];
                    pq[nt][0] += C[mt][nt][0] * C[mt][nt][0] + C[mt][nt][2] * C[mt][nt][2];
                    pq[nt][1] += C[mt][nt][1] * C[mt][nt][1] + C[mt][nt][3] * C[mt][nt][3];
                }
            }
            #pragma unroll
            for (int nt = 0; nt < 4; nt++)
                #pragma unroll
                for (int cp = 0; cp < 2; cp++) {
                    ps[nt][cp] += __shfl_xor_sync(0xFFFFFFFFu, ps[nt][cp], 4);
                    ps[nt][cp] += __shfl_xor_sync(0xFFFFFFFFu, ps[nt][cp], 8);
                    ps[nt][cp] += __shfl_xor_sync(0xFFFFFFFFu, ps[nt][cp], 16);
                    pq[nt][cp] += __shfl_xor_sync(0xFFFFFFFFu, pq[nt][cp], 4);
                    pq[nt][cp] += __shfl_xor_sync(0xFFFFFFFFu, pq[nt][cp], 8);
                    pq[nt][cp] += __shfl_xor_sync(0xFFFFFFFFu, pq[nt][cp], 16);
                }
            if (lane < 4) {
                #pragma unroll
                for (int nt = 0; nt < 4; nt++) {
                    int cc = nbase + nt * 8 + 2 * lane;
                    sPS[wrow * 128 + cc]     = ps[nt][0];
                    sPS[wrow * 128 + cc + 1] = ps[nt][1];
                    sPQ[wrow * 128 + cc]     = pq[nt][0];
                    sPQ[wrow * 128 + cc + 1] = pq[nt][1];
                }
            }
        }
        __syncthreads();
        if (tid < 128) {
            float s  = sPS[tid] + sPS[128 + tid] + sPS[256 + tid] + sPS[384 + tid];
            float sq = sPQ[tid] + sPQ[128 + tid] + sPQ[256 + tid] + sPQ[384 + tid];
            float mean = s * (1.0f / 128.0f);
            float var = sq * (1.0f / 128.0f) - mean * mean;
            sStat[tid * 2] = mean;
            sStat[tid * 2 + 1] = rsqrtf(var + LN_EPS);
        }
        __syncthreads();

        {   // apply LN from fragments, store to global
            float* ob = out + (size_t)b * NCH * NW + n0;
            #pragma unroll
            for (int mt = 0; mt < 2; mt++) {
                int r0 = mbase + mt * 16 + (lane >> 2);
                int r1 = r0 + 8;
                float g0 = sGamma[r0], be0 = sBeta[r0];
                float g1 = sGamma[r1], be1 = sBeta[r1];
                #pragma unroll
                for (int nt = 0; nt < 4; nt++) {
                    int cc = nbase + nt * 8 + 2 * (lane & 3);
                    float m0 = sStat[2 * cc],       rs0 = sStat[2 * cc + 1];
                    float m1 = sStat[2 * (cc + 1)], rs1 = sStat[2 * (cc + 1) + 1];
                    *(float2*)(ob + (size_t)r0 * NW + cc) = make_float2(
                        (C[mt][nt][0] - m0) * rs0 * g0 + be0,
                        (C[mt][nt][1] - m1) * rs1 * g0 + be0);
                    *(float2*)(ob + (size_t)r1 * NW + cc) = make_float2(
                        (C[mt][nt][2] - m0) * rs0 * g1 + be1,
                        (C[mt][nt][3] - m1) * rs1 * g1 + be1);
                }
            }
        }
    }
}

// ---------------------------------------------------------------------------
extern "C" void kernel_launch(void* const* d_in, const int* in_sizes, int n_in,
                              void* d_out, int out_size) {
    const float* x    = (const float*)d_in[0];
    const float* Wqkv = (const float*)d_in[1];
    const float* Wout = (const float*)d_in[2];
    const float* bo   = (const float*)d_in[3];
    const float* gm   = (const float*)d_in[4];
    const float* bt   = (const float*)d_in[5];
    float* out = (float*)d_out;

    const int SMEM_A = 229376;
    const int SMEM_C = 196608;
    cudaFuncSetAttribute(k_kvctx, cudaFuncAttributeMaxDynamicSharedMemorySize, SMEM_A);
    cudaFuncSetAttribute(k_qout,  cudaFuncAttributeMaxDynamicSharedMemorySize, SMEM_C);

    k_zero<<<66, 1024>>>();
    k_kvctx<<<GRID_SM, 256, SMEM_A>>>(x, Wqkv);
    k_mbuild<<<dim3(8, 16), 256>>>(Wout);
    k_qout<<<GRID_SM, 512, SMEM_C>>>(x, Wqkv, bo, gm, bt, out);
}

// round 16
// speedup vs baseline: 1.5371x; 1.0320x over previous
#include <cuda_runtime.h>
#include <cstdint>

#define NB 16
#define NCH 128
#define NW 16384
#define NTILES 4096
#define GRID_SM 152
#define SCALE_F 0.17677669529663687f
#define LN_EPS 1e-5f

__device__ float g_S[NB * 4096];
__device__ float g_Z[NB * 128];
__device__ float g_M[NB * 128 * 128];

__device__ __forceinline__ uint32_t smem_u32(const void* p) {
    uint32_t a;
    asm("{ .reg .u64 t; cvta.to.shared.u64 t, %1; cvt.u32.u64 %0, t; }" : "=r"(a) : "l"(p));
    return a;
}
__device__ __forceinline__ void bf16_split2(float a, float b, uint32_t& h, uint32_t& l) {
    asm("cvt.rn.bf16x2.f32 %0, %1, %2;" : "=r"(h) : "f"(b), "f"(a));
    float ra = a - __uint_as_float(h << 16);
    float rb = b - __uint_as_float(h & 0xFFFF0000u);
    asm("cvt.rn.bf16x2.f32 %0, %1, %2;" : "=r"(l) : "f"(rb), "f"(ra));
}
__device__ __forceinline__ void ldsm_x4(uint32_t* a, uint32_t addr) {
    asm volatile("ldmatrix.sync.aligned.m8n8.x4.shared.b16 {%0,%1,%2,%3}, [%4];"
                 : "=r"(a[0]), "=r"(a[1]), "=r"(a[2]), "=r"(a[3]) : "r"(addr));
}
__device__ __forceinline__ void ldsm_x4t(uint32_t* a, uint32_t addr) {
    asm volatile("ldmatrix.sync.aligned.m8n8.x4.trans.shared.b16 {%0,%1,%2,%3}, [%4];"
                 : "=r"(a[0]), "=r"(a[1]), "=r"(a[2]), "=r"(a[3]) : "r"(addr));
}
__device__ __forceinline__ void mma16816(float* c, const uint32_t* a, const uint32_t* b) {
    asm volatile("mma.sync.aligned.m16n8k16.row.col.f32.bf16.bf16.f32 "
                 "{%0,%1,%2,%3},{%4,%5,%6,%7},{%8,%9},{%0,%1,%2,%3};"
                 : "+f"(c[0]), "+f"(c[1]), "+f"(c[2]), "+f"(c[3])
                 : "r"(a[0]), "r"(a[1]), "r"(a[2]), "r"(a[3]), "r"(b[0]), "r"(b[1]));
}
__device__ __forceinline__ void cp_async16(uint32_t dst, const void* src) {
    asm volatile("cp.async.cg.shared.global [%0], [%1], 16;" :: "r"(dst), "l"(src));
}

// fp32 rows of 128 -> two bf16 planes in smem, rows of 256B, XOR-16B swizzle
__device__ __forceinline__ void w_row_sts(char* sm, uint32_t oh, uint32_t ol,
                                          const float* __restrict__ src,
                                          int nrows, int tid, int nthreads) {
    for (int idx = tid * 4; idx < nrows * 128; idx += nthreads * 4) {
        int m = idx >> 7, k = idx & 127;
        float4 w = *(const float4*)(src + m * 128 + k);
        uint32_t h0, l0, h1, l1;
        bf16_split2(w.x, w.y, h0, l0);
        bf16_split2(w.z, w.w, h1, l1);
        uint32_t byte = (uint32_t)(m * 256) + (((uint32_t)(k * 2)) ^ (((uint32_t)m & 7) << 4));
        *(uint2*)(sm + oh + byte) = make_uint2(h0, h1);
        *(uint2*)(sm + ol + byte) = make_uint2(l0, l1);
    }
}

// ---------------------------------------------------------------------------
__global__ void k_zero() {
    int i = blockIdx.x * blockDim.x + threadIdx.x;
    if (i < NB * 4096) g_S[i] = 0.0f;
    else g_Z[i - NB * 4096] = 0.0f;
}

// ---------------------------------------------------------------------------
// k_kvctx: full bf16x3 numerics (R10); NOW 512 threads for latency hiding.
// Main GEMM warp grid 8x2 (32Mx32N/warp); S-GEMM warp = (head, d-half, e-half).
#define O_XHI 131072u
#define O_XLO 147456u
#define O_EKH 163840u
#define O_EKL 180224u
#define O_VH  196608u
#define O_VL  212992u

__global__ void __launch_bounds__(512, 1)
k_kvctx(const float* __restrict__ x, const float* __restrict__ Wqkv) {
    extern __shared__ char sm[];
    const uint32_t smb = smem_u32(sm);
    const int tid = threadIdx.x, wid = tid >> 5, lane = tid & 31;
    const int mbase = (wid >> 1) * 32;   // 8 warp-rows of 32 M rows
    const int nbase = (wid & 1) * 32;    // 2 warp-cols of 32 N cols
    const int h = wid >> 2;              // S-GEMM: head
    const int mh = (wid >> 1) & 1;       // S-GEMM: d-half (16 rows)
    const int et = wid & 1;              // S-GEMM: e-half (16 cols)

    w_row_sts(sm, 0u, 65536u, Wqkv + 128 * 128, 256, tid, 512);

    int per = (NTILES + GRID_SM - 1) / GRID_SM;   // 27
    int lo = blockIdx.x * per, hi = min(NTILES, lo + per);

    float CS[2][4];      // 16d x 16e register S accumulator
    float zacc[4];       // per-mt row-half Z partials (this warp's 32 cols)
    int curb = -1;

    float4 px[4];
    if (lo < hi) {
        const float* xb = x + (size_t)(lo >> 8) * NCH * NW + (size_t)(lo & 255) * 64;
        #pragma unroll
        for (int it = 0; it < 4; it++) {
            int idx = tid * 4 + it * 2048;
            px[it] = *(const float4*)(xb + (size_t)(idx >> 6) * NW + (idx & 63));
        }
    }

    for (int tile = lo; tile < hi; tile++) {
        int b = tile >> 8;
        if (b != curb) {
            if (curb >= 0) {   // flush S and Z for curb
                float* gS = g_S + curb * 4096 + h * 1024;
                int d0 = mh * 16 + (lane >> 2);
                #pragma unroll
                for (int nt = 0; nt < 2; nt++) {
                    int e = et * 16 + nt * 8 + 2 * (lane & 3);
                    atomicAdd(gS + d0 * 32 + e,           CS[nt][0]);
                    atomicAdd(gS + d0 * 32 + e + 1,       CS[nt][1]);
                    atomicAdd(gS + (d0 + 8) * 32 + e,     CS[nt][2]);
                    atomicAdd(gS + (d0 + 8) * 32 + e + 1, CS[nt][3]);
                }
                if (mbase < 128 && (lane & 3) == 0) {
                    #pragma unroll
                    for (int mt = 0; mt < 2; mt++) {
                        atomicAdd(g_Z + curb * 128 + mbase + mt * 16 + (lane >> 2),     zacc[mt * 2]);
                        atomicAdd(g_Z + curb * 128 + mbase + mt * 16 + (lane >> 2) + 8, zacc[mt * 2 + 1]);
                    }
                }
            }
            #pragma unroll
            for (int nt = 0; nt < 2; nt++)
                #pragma unroll
                for (int q = 0; q < 4; q++) CS[nt][q] = 0.0f;
            zacc[0] = zacc[1] = zacc[2] = zacc[3] = 0.0f;
            curb = b;
        }

        // STS x (hi/lo planes) from prefetched regs
        #pragma unroll
        for (int it = 0; it < 4; it++) {
            int idx = tid * 4 + it * 2048;
            int k = idx >> 6, n = idx & 63;
            uint32_t h0, l0, h1, l1;
            bf16_split2(px[it].x, px[it].y, h0, l0);
            bf16_split2(px[it].z, px[it].w, h1, l1);
            uint32_t byte = (uint32_t)(k * 128) + (((uint32_t)(n * 2)) ^ (((uint32_t)k & 7) << 4));
            *(uint2*)(sm + O_XHI + byte) = make_uint2(h0, h1);
            *(uint2*)(sm + O_XLO + byte) = make_uint2(l0, l1);
        }
        if (tile + 1 < hi) {
            int nt2 = tile + 1;
            const float* xb = x + (size_t)(nt2 >> 8) * NCH * NW + (size_t)(nt2 & 255) * 64;
            #pragma unroll
            for (int it = 0; it < 4; it++) {
                int idx = tid * 4 + it * 2048;
                px[it] = *(const float4*)(xb + (size_t)(idx >> 6) * NW + (idx & 63));
            }
        }
        __syncthreads();   // x staged; prior S-GEMM reads of ek/v complete

        // main GEMM: kv(256x64) = W_kv @ x, full bf16x3, 32x32 warp tile
        float C[2][4][4];
        #pragma unroll
        for (int i = 0; i < 2; i++)
            #pragma unroll
            for (int j = 0; j < 4; j++)
                #pragma unroll
                for (int q = 0; q < 4; q++) C[i][j][q] = 0.0f;

        #pragma unroll
        for (int ks = 0; ks < 8; ks++) {
            int k0 = ks * 16;
            uint32_t ah[2][4], al[2][4], bh[2][4], bl[2][4];
            #pragma unroll
            for (int mt = 0; mt < 2; mt++) {
                int row = mbase + mt * 16 + (lane & 15);
                uint32_t kb = (uint32_t)((k0 + ((lane >> 4) << 3)) * 2);
                uint32_t off = (uint32_t)(row * 256) + (kb ^ (((uint32_t)row & 7) << 4));
                ldsm_x4(ah[mt], smb + off);
                ldsm_x4(al[mt], smb + 65536u + off);
            }
            #pragma unroll
            for (int t2 = 0; t2 < 2; t2++) {
                int krow = k0 + (lane & 15);
                uint32_t nb = (uint32_t)((nbase + t2 * 16 + ((lane >> 4) << 3)) * 2);
                uint32_t off = (uint32_t)(krow * 128) + (nb ^ (((uint32_t)krow & 7) << 4));
                ldsm_x4t(bh[t2], smb + O_XHI + off);
                ldsm_x4t(bl[t2], smb + O_XLO + off);
            }
            #pragma unroll
            for (int mt = 0; mt < 2; mt++)
                #pragma unroll
                for (int t2 = 0; t2 < 2; t2++) {
                    mma16816(C[mt][t2 * 2],     ah[mt], &bh[t2][0]);
                    mma16816(C[mt][t2 * 2 + 1], ah[mt], &bh[t2][2]);
                    mma16816(C[mt][t2 * 2],     ah[mt], &bl[t2][0]);
                    mma16816(C[mt][t2 * 2 + 1], ah[mt], &bl[t2][2]);
                    mma16816(C[mt][t2 * 2],     al[mt], &bh[t2][0]);
                    mma16816(C[mt][t2 * 2 + 1], al[mt], &bh[t2][2]);
                }
        }

        // epilogue: warps with mbase<128 -> exp(k) quadrant; else v quadrant
        if (mbase < 128) {
            float zp[4] = {0.0f, 0.0f, 0.0f, 0.0f};
            #pragma unroll
            for (int mt = 0; mt < 2; mt++) {
                int r0 = mbase + mt * 16 + (lane >> 2);
                int r1 = r0 + 8;
                #pragma unroll
                for (int nt = 0; nt < 4; nt++) {
                    int cc = nbase + nt * 8 + 2 * (lane & 3);
                    float e0 = __expf(C[mt][nt][0]);
                    float e1 = __expf(C[mt][nt][1]);
                    float e2 = __expf(C[mt][nt][2]);
                    float e3 = __expf(C[mt][nt][3]);
                    zp[mt * 2]     += e0 + e1;
                    zp[mt * 2 + 1] += e2 + e3;
                    uint32_t hh, ll;
                    bf16_split2(e0, e1, hh, ll);
                    uint32_t byte = (uint32_t)(r0 * 128)
                                  + (((uint32_t)(cc * 2)) ^ (((uint32_t)r0 & 7) << 4));
                    *(uint32_t*)(sm + O_EKH + byte) = hh;
                    *(uint32_t*)(sm + O_EKL + byte) = ll;
                    bf16_split2(e2, e3, hh, ll);
                    byte = (uint32_t)(r1 * 128)
                         + (((uint32_t)(cc * 2)) ^ (((uint32_t)r1 & 7) << 4));
                    *(uint32_t*)(sm + O_EKH + byte) = hh;
                    *(uint32_t*)(sm + O_EKL + byte) = ll;
                }
            }
            #pragma unroll
            for (int i = 0; i < 4; i++) {
                zp[i] += __shfl_xor_sync(0xFFFFFFFFu, zp[i], 1);
                zp[i] += __shfl_xor_sync(0xFFFFFFFFu, zp[i], 2);
                zacc[i] += zp[i];
            }
        } else {
            #pragma unroll
            for (int mt = 0; mt < 2; mt++) {
                int r0 = mbase - 128 + mt * 16 + (lane >> 2);
                int r1 = r0 + 8;
                #pragma unroll
                for (int nt = 0; nt < 4; nt++) {
                    int cc = nbase + nt * 8 + 2 * (lane & 3);
                    uint32_t hh, ll;
                    bf16_split2(C[mt][nt][0], C[mt][nt][1], hh, ll);
                    uint32_t byte = (uint32_t)(r0 * 128)
                                  + (((uint32_t)(cc * 2)) ^ (((uint32_t)r0 & 7) << 4));
                    *(uint32_t*)(sm + O_VH + byte) = hh;
                    *(uint32_t*)(sm + O_VL + byte) = ll;
                    bf16_split2(C[mt][nt][2], C[mt][nt][3], hh, ll);
                    byte = (uint32_t)(r1 * 128)
                         + (((uint32_t)(cc * 2)) ^ (((uint32_t)r1 & 7) << 4));
                    *(uint32_t*)(sm + O_VH + byte) = hh;
                    *(uint32_t*)(sm + O_VL + byte) = ll;
                }
            }
        }
        __syncthreads();   // ek/v complete

        {   // S-GEMM: warp = (h, mh, et); 16d x 16e output; full bf16x3
            int arow = h * 32 + mh * 16 + (lane & 15);
            uint32_t acol = (uint32_t)((lane >> 4) << 4);
            int erow_in = ((lane >> 4) << 3) + (lane & 7);
            uint32_t bsel = (uint32_t)(((lane >> 3) & 1) << 4);
            int er = h * 32 + et * 16 + erow_in;
            #pragma unroll
            for (int ks = 0; ks < 4; ks++) {
                uint32_t kb = (uint32_t)(ks * 32);
                uint32_t aoff = (uint32_t)(arow * 128)
                              + ((kb + acol) ^ (((uint32_t)arow & 7) << 4));
                uint32_t Ah[4], Al[4];
                ldsm_x4(Ah, smb + O_EKH + aoff);
                ldsm_x4(Al, smb + O_EKL + aoff);
                uint32_t boff = (uint32_t)(er * 128)
                              + ((kb + bsel) ^ (((uint32_t)er & 7) << 4));
                uint32_t Bh[4], Bl[4];
                ldsm_x4(Bh, smb + O_VH + boff);
                ldsm_x4(Bl, smb + O_VL + boff);
                mma16816(CS[0], Ah, &Bh[0]);
                mma16816(CS[1], Ah, &Bh[2]);
                mma16816(CS[0], Ah, &Bl[0]);
                mma16816(CS[1], Ah, &Bl[2]);
                mma16816(CS[0], Al, &Bh[0]);
                mma16816(CS[1], Al, &Bh[2]);
            }
        }
    }

    // final flush
    if (curb >= 0) {
        float* gS = g_S + curb * 4096 + h * 1024;
        int d0 = mh * 16 + (lane >> 2);
        #pragma unroll
        for (int nt = 0; nt < 2; nt++) {
            int e = et * 16 + nt * 8 + 2 * (lane & 3);
            atomicAdd(gS + d0 * 32 + e,           CS[nt][0]);
            atomicAdd(gS + d0 * 32 + e + 1,       CS[nt][1]);
            atomicAdd(gS + (d0 + 8) * 32 + e,     CS[nt][2]);
            atomicAdd(gS + (d0 + 8) * 32 + e + 1, CS[nt][3]);
        }
        if (mbase < 128 && (lane & 3) == 0) {
            #pragma unroll
            for (int mt = 0; mt < 2; mt++) {
                atomicAdd(g_Z + curb * 128 + mbase + mt * 16 + (lane >> 2),     zacc[mt * 2]);
                atomicAdd(g_Z + curb * 128 + mbase + mt * 16 + (lane >> 2) + 8, zacc[mt * 2 + 1]);
            }
        }
    }
}

// ---------------------------------------------------------------------------
__global__ void k_mbuild(const float* __restrict__ Wout) {
    __shared__ float sCtx[4096];
    __shared__ float sWo[16 * 128];
    int b = blockIdx.y, o0 = blockIdx.x * 16;
    int tid = threadIdx.x;
    for (int idx = tid * 4; idx < 4096; idx += 1024) {
        float4 sv = *(const float4*)(g_S + b * 4096 + idx);
        float z = g_Z[b * 128 + (idx >> 5)];
        float r = 1.0f / (z * (float)NW);
        sv.x *= r; sv.y *= r; sv.z *= r; sv.w *= r;
        *(float4*)(sCtx + idx) = sv;
    }
    for (int idx = tid * 4; idx < 2048; idx += 1024)
        *(float4*)(sWo + idx) = *(const float4*)(Wout + (size_t)o0 * 128 + idx);
    __syncthreads();
    for (int idx = tid; idx < 2048; idx += 256) {
        int orr = idx >> 7, hd = idx & 127;
        int hh = hd >> 5, d = hd & 31;
        const float* wrow = sWo + orr * 128 + hh * 32;
        const float* crow = sCtx + hh * 1024 + d * 32;
        float sum = 0.0f;
        #pragma unroll
        for (int e4 = 0; e4 < 8; e4++) {
            float4 w4 = *(const float4*)(wrow + e4 * 4);
            float4 c4 = *(const float4*)(crow + e4 * 4);
            sum += w4.x * c4.x + w4.y * c4.y + w4.z * c4.z + w4.w * c4.w;
        }
        g_M[b * 16384 + (o0 + orr) * 128 + hd] = SCALE_F * sum;
    }
}

// ---------------------------------------------------------------------------
// k_qout: EXACT R10 (best passing config, full bf16x3 everywhere)
#define Q_STG 163840u

__global__ void __launch_bounds__(512, 1)
k_qout(const float* __restrict__ x, const float* __restrict__ Wqkv,
       const float* __restrict__ b_out, const float* __restrict__ gamma,
       const float* __restrict__ beta, float* __restrict__ out) {
    extern __shared__ char sm[];
    __shared__ float sBias[128], sGamma[128], sBeta[128], sStat[128];
    __shared__ float sPS[256], sPQ[256];
    const uint32_t smb = smem_u32(sm);
    const int tid = threadIdx.x, wid = tid >> 5, lane = tid & 31;
    const int mbase = (wid >> 2) * 32;
    const int nbase = (wid & 3) * 16;
    const int wrow = wid >> 2;

    w_row_sts(sm, 0u, 32768u, Wqkv, 128, tid, 512);
    if (tid < 128) {
        sBias[tid] = b_out[tid]; sGamma[tid] = gamma[tid]; sBeta[tid] = beta[tid];
    }

    int per = (NTILES + GRID_SM - 1) / GRID_SM;
    int lo = blockIdx.x * per, hi = min(NTILES, lo + per);
    int curb = -1;

    for (int tile = lo; tile < hi; tile++) {
        int b = tile >> 8, n0 = (tile & 255) * 64;
        if (b != curb) {
            __syncthreads();
            w_row_sts(sm, 65536u, 98304u, g_M + (size_t)b * 16384, 128, tid, 512);
            curb = b;
        }
        __syncthreads();

        if (tile == lo) {
            const float* xb = x + (size_t)b * NCH * NW + n0;
            #pragma unroll
            for (int it = 0; it < 4; it++) {
                int idx = tid * 4 + it * 2048;
                int k = idx >> 6, n = idx & 63;
                float4 v = *(const float4*)(xb + (size_t)k * NW + n);
                uint32_t h0, l0, h1, l1;
                bf16_split2(v.x, v.y, h0, l0);
                bf16_split2(v.z, v.w, h1, l1);
                uint32_t byte = (uint32_t)(k * 128) + (((uint32_t)(n * 2)) ^ (((uint32_t)k & 7) << 4));
                *(uint2*)(sm + 131072u + byte) = make_uint2(h0, h1);
                *(uint2*)(sm + 147456u + byte) = make_uint2(l0, l1);
            }
        } else {
            asm volatile("cp.async.wait_group 0;" ::: "memory");
            #pragma unroll
            for (int it = 0; it < 4; it++) {
                int idx = tid * 4 + it * 2048;
                int k = idx >> 6, n = idx & 63;
                float4 v = *(const float4*)(sm + Q_STG + (uint32_t)idx * 4u);
                uint32_t h0, l0, h1, l1;
                bf16_split2(v.x, v.y, h0, l0);
                bf16_split2(v.z, v.w, h1, l1);
                uint32_t byte = (uint32_t)(k * 128) + (((uint32_t)(n * 2)) ^ (((uint32_t)k & 7) << 4));
                *(uint2*)(sm + 131072u + byte) = make_uint2(h0, h1);
                *(uint2*)(sm + 147456u + byte) = make_uint2(l0, l1);
            }
        }
        __syncthreads();

        if (tile + 1 < hi) {
            int nt2 = tile + 1;
            const float* xb = x + (size_t)(nt2 >> 8) * NCH * NW + (size_t)(nt2 & 255) * 64;
            #pragma unroll
            for (int it = 0; it < 4; it++) {
                int idx = tid * 4 + it * 2048;
                cp_async16(smb + Q_STG + (uint32_t)idx * 4u,
                           xb + (size_t)(idx >> 6) * NW + (idx & 63));
            }
            asm volatile("cp.async.commit_group;" ::: "memory");
        }

        float C[2][2][4];
        #define DO_GEMM(ABASE0)                                                          \
        do {                                                                             \
            _Pragma("unroll")                                                            \
            for (int i = 0; i < 2; i++)                                                  \
                _Pragma("unroll")                                                        \
                for (int j = 0; j < 2; j++)                                              \
                    _Pragma("unroll")                                                    \
                    for (int q = 0; q < 4; q++) C[i][j][q] = 0.0f;                       \
            _Pragma("unroll")                                                            \
            for (int ks = 0; ks < 8; ks++) {                                             \
                int k0 = ks * 16;                                                        \
                uint32_t ah[2][4], al[2][4], bh[4], bl[4];                               \
                _Pragma("unroll")                                                        \
                for (int mt = 0; mt < 2; mt++) {                                         \
                    int row = mbase + mt * 16 + (lane & 15);                             \
                    uint32_t kb = (uint32_t)((k0 + ((lane >> 4) << 3)) * 2);             \
                    uint32_t off = (uint32_t)(row * 256)                                 \
                                 + (kb ^ (((uint32_t)row & 7) << 4));                    \
                    ldsm_x4(ah[mt], smb + (ABASE0) + off);                               \
                    ldsm_x4(al[mt], smb + (ABASE0) + 32768u + off);                      \
                }                                                                        \
                {                                                                        \
                    int krow = k0 + (lane & 15);                                         \
                    uint32_t nb = (uint32_t)((nbase + ((lane >> 4) << 3)) * 2);          \
                    uint32_t off = (uint32_t)(krow * 128)                                \
                                 + (nb ^ (((uint32_t)krow & 7) << 4));                   \
                    ldsm_x4t(bh, smb + 131072u + off);                                   \
                    ldsm_x4t(bl, smb + 147456u + off);                                   \
                }                                                                        \
                _Pragma("unroll")                                                        \
                for (int mt = 0; mt < 2; mt++) {                                         \
                    mma16816(C[mt][0], ah[mt], &bh[0]);                                  \
                    mma16816(C[mt][1], ah[mt], &bh[2]);                                  \
                    mma16816(C[mt][0], ah[mt], &bl[0]);                                  \
                    mma16816(C[mt][1], ah[mt], &bl[2]);                                  \
                    mma16816(C[mt][0], al[mt], &bh[0]);                                  \
                    mma16816(C[mt][1], al[mt], &bh[2]);                                  \
                }                                                                        \
            }                                                                            \
        } while (0)

        DO_GEMM(0u);
        __syncthreads();

        {   // softmax over head-dim (warp rows = one head, 32 rows)
            #pragma unroll
            for (int nt = 0; nt < 2; nt++) {
                float p0 = 0.0f, p1 = 0.0f;
                #pragma unroll
                for (int mt = 0; mt < 2; mt++) {
                    #pragma unroll
                    for (int q = 0; q < 4; q++) C[mt][nt][q] = __expf(C[mt][nt][q]);
                    p0 += C[mt][nt][0] + C[mt][nt][2];
                    p1 += C[mt][nt][1] + C[mt][nt][3];
                }
                p0 += __shfl_xor_sync(0xFFFFFFFFu, p0, 4);
                p0 += __shfl_xor_sync(0xFFFFFFFFu, p0, 8);
                p0 += __shfl_xor_sync(0xFFFFFFFFu, p0, 16);
                p1 += __shfl_xor_sync(0xFFFFFFFFu, p1, 4);
                p1 += __shfl_xor_sync(0xFFFFFFFFu, p1, 8);
                p1 += __shfl_xor_sync(0xFFFFFFFFu, p1, 16);
                float r0 = __fdividef(1.0f, p0), r1 = __fdividef(1.0f, p1);
                #pragma unroll
                for (int mt = 0; mt < 2; mt++) {
                    C[mt][nt][0] *= r0; C[mt][nt][2] *= r0;
                    C[mt][nt][1] *= r1; C[mt][nt][3] *= r1;
                }
            }
            #pragma unroll
            for (int mt = 0; mt < 2; mt++)
                #pragma unroll
                for (int nt = 0; nt < 2; nt++) {
                    int r0 = mbase + mt * 16 + (lane >> 2);
                    int cc = nbase + nt * 8 + 2 * (lane & 3);
                    uint32_t hh, ll;
                    bf16_split2(C[mt][nt][0], C[mt][nt][1], hh, ll);
                    uint32_t byte = (uint32_t)(r0 * 128)
                                  + (((uint32_t)(cc * 2)) ^ (((uint32_t)r0 & 7) << 4));
                    *(uint32_t*)(sm + 131072 + byte) = hh;
                    *(uint32_t*)(sm + 147456 + byte) = ll;
                    int r1 = r0 + 8;
                    bf16_split2(C[mt][nt][2], C[mt][nt][3], hh, ll);
                    byte = (uint32_t)(r1 * 128)
                         + (((uint32_t)(cc * 2)) ^ (((uint32_t)r1 & 7) << 4));
                    *(uint32_t*)(sm + 131072 + byte) = hh;
                    *(uint32_t*)(sm + 147456 + byte) = ll;
                }
        }
        __syncthreads();

        DO_GEMM(65536u);
        #undef DO_GEMM

        {   // bias + LN partials from fragments
            float ps[2][2], pq[2][2];
            #pragma unroll
            for (int nt = 0; nt < 2; nt++) { ps[nt][0] = ps[nt][1] = pq[nt][0] = pq[nt][1] = 0.0f; }
            #pragma unroll
            for (int mt = 0; mt < 2; mt++) {
                int r0 = mbase + mt * 16 + (lane >> 2);
                float b0 = sBias[r0], b1 = sBias[r0 + 8];
                #pragma unroll
                for (int nt = 0; nt < 2; nt++) {
                    C[mt][nt][0] += b0; C[mt][nt][1] += b0;
                    C[mt][nt][2] += b1; C[mt][nt][3] += b1;
                    ps[nt][0] += C[mt][nt][0] + C[mt][nt][2];
                    ps[nt][1] += C[mt][nt][1] + C[mt][nt][3];
                    pq[nt][0] += C[mt][nt][0] * C[mt][nt][0] + C[mt][nt][2] * C[mt][nt][2];
                    pq[nt][1] += C[mt][nt][1] * C[mt][nt][1] + C[mt][nt][3] * C[mt][nt][3];
                }
            }
            #pragma unroll
            for (int nt = 0; nt < 2; nt++)
                #pragma unroll
                for (int cp = 0; cp < 2; cp++) {
                    ps[nt][cp] += __shfl_xor_sync(0xFFFFFFFFu, ps[nt][cp], 4);
                    ps[nt][cp] += __shfl_xor_sync(0xFFFFFFFFu, ps[nt][cp], 8);
                    ps[nt][cp] += __shfl_xor_sync(0xFFFFFFFFu, ps[nt][cp], 16);
                    pq[nt][cp] += __shfl_xor_sync(0xFFFFFFFFu, pq[nt][cp], 4);
                    pq[nt][cp] += __shfl_xor_sync(0xFFFFFFFFu, pq[nt][cp], 8);
                    pq[nt][cp] += __shfl_xor_sync(0xFFFFFFFFu, pq[nt][cp], 16);
                }
            if (lane < 4) {
                #pragma unroll
                for (int nt = 0; nt < 2; nt++) {
                    int cc = nbase + nt * 8 + 2 * lane;
                    sPS[wrow * 64 + cc]     = ps[nt][0];
                    sPS[wrow * 64 + cc + 1] = ps[nt][1];
                    sPQ[wrow * 64 + cc]     = pq[nt][0];
                    sPQ[wrow * 64 + cc + 1] = pq[nt][1];
                }
            }
        }
        __syncthreads();
        if (tid < 64) {
            float s  = sPS[tid] + sPS[64 + tid] + sPS[128 + tid] + sPS[192 + tid];
            float sq = sPQ[tid] + sPQ[64 + tid] + sPQ[128 + tid] + sPQ[192 + tid];
            float mean = s * (1.0f / 128.0f);
            float var = sq * (1.0f / 128.0f) - mean * mean;
            sStat[tid * 2] = mean;
            sStat[tid * 2 + 1] = rsqrtf(var + LN_EPS);
        }
        __syncthreads();

        {   // apply LN from fragments, store to global
            float* ob = out + (size_t)b * NCH * NW + n0;
            #pragma unroll
            for (int mt = 0; mt < 2; mt++) {
                int r0 = mbase + mt * 16 + (lane >> 2);
                int r1 = r0 + 8;
                float g0 = sGamma[r0], be0 = sBeta[r0];
                float g1 = sGamma[r1], be1 = sBeta[r1];
                #pragma unroll
                for (int nt = 0; nt < 2; nt++) {
                    int cc = nbase + nt * 8 + 2 * (lane & 3);
                    float m0 = sStat[2 * cc],       rs0 = sStat[2 * cc + 1];
                    float m1 = sStat[2 * (cc + 1)], rs1 = sStat[2 * (cc + 1) + 1];
                    *(float2*)(ob + (size_t)r0 * NW + cc) = make_float2(
                        (C[mt][nt][0] - m0) * rs0 * g0 + be0,
                        (C[mt][nt][1] - m1) * rs1 * g0 + be0);
                    *(float2*)(ob + (size_t)r1 * NW + cc) = make_float2(
                        (C[mt][nt][2] - m0) * rs0 * g1 + be1,
                        (C[mt][nt][3] - m1) * rs1 * g1 + be1);
                }
            }
        }
    }
}

// ---------------------------------------------------------------------------
extern "C" void kernel_launch(void* const* d_in, const int* in_sizes, int n_in,
                              void* d_out, int out_size) {
    const float* x    = (const float*)d_in[0];
    const float* Wqkv = (const float*)d_in[1];
    const float* Wout = (const float*)d_in[2];
    const float* bo   = (const float*)d_in[3];
    const float* gm   = (const float*)d_in[4];
    const float* bt   = (const float*)d_in[5];
    float* out = (float*)d_out;

    const int SMEM_A = 229376;
    const int SMEM_C = 196608;
    cudaFuncSetAttribute(k_kvctx, cudaFuncAttributeMaxDynamicSharedMemorySize, SMEM_A);
    cudaFuncSetAttribute(k_qout,  cudaFuncAttributeMaxDynamicSharedMemorySize, SMEM_C);

    k_zero<<<66, 1024>>>();
    k_kvctx<<<GRID_SM, 512, SMEM_A>>>(x, Wqkv);
    k_mbuild<<<dim3(8, 16), 256>>>(Wout);
    k_qout<<<GRID_SM, 512, SMEM_C>>>(x, Wqkv, bo, gm, bt, out);
}